// round 1
// baseline (speedup 1.0000x reference)
#include <cuda_runtime.h>
#include <cuda_bf16.h>

// Problem constants (shapes fixed by the reference)
#define NNODES 15360       // 512 graphs * 30 nodes
#define HID 64
#define EMAX 41984         // 2 * 512 * 41
#define NLAYERS 5
#define QCOLS 2112         // 32*64 (w-part) + 64 (b2-part)

// -------- scratch (device globals; no allocation allowed) --------
__device__ float g_h0[NNODES * HID];
__device__ float g_h1[NNODES * HID];
__device__ float g_Q[(size_t)NNODES * QCOLS];       // ~130 MB
__device__ float g_z[EMAX * 32];
__device__ float g_agg[NNODES * HID];
__device__ float g_deg[NNODES];
__device__ float g_invdeg[NNODES];
__device__ float g_W2p[NLAYERS * HID * QCOLS];

// -------- small utility kernels --------
__global__ void k_zero(float* p, int n) {
    int i = blockIdx.x * blockDim.x + threadIdx.x;
    if (i < n) p[i] = 0.f;
}

// W2p[l][h][j*64+o] = W2[l][j][h*64+o];  W2p[l][h][2048+o] = b2[l][h*64+o]
__global__ void k_w2p(const float* __restrict__ W2, const float* __restrict__ b2) {
    int idx = blockIdx.x * blockDim.x + threadIdx.x;
    const int total = NLAYERS * HID * QCOLS;
    if (idx >= total) return;
    int c = idx % QCOLS;
    int h = (idx / QCOLS) % HID;
    int l = idx / (QCOLS * HID);
    float v;
    if (c < 2048) {
        int j = c >> 6, o = c & 63;
        v = W2[(size_t)(l * 32 + j) * 4096 + h * 64 + o];
    } else {
        int o = c - 2048;
        v = b2[(size_t)l * 4096 + h * 64 + o];
    }
    g_W2p[idx] = v;
}

// h0 = x @ Wp + bp   (x: [N,8], Wp: [8,64])
__global__ void k_proj(const float* __restrict__ x, const float* __restrict__ Wp,
                       const float* __restrict__ bp, float* __restrict__ h, int N) {
    int t = blockIdx.x * blockDim.x + threadIdx.x;
    if (t >= N * HID) return;
    int n = t >> 6, c = t & 63;
    const float* xr = x + n * 8;
    float acc = bp[c];
#pragma unroll
    for (int k = 0; k < 8; k++) acc += xr[k] * Wp[k * 64 + c];
    h[t] = acc;
}

__global__ void k_deg(const int* __restrict__ dst, float* __restrict__ deg, int E) {
    int e = blockIdx.x * blockDim.x + threadIdx.x;
    if (e < E) atomicAdd(&deg[dst[e]], 1.0f);
}

__global__ void k_invdeg(const float* __restrict__ deg, float* __restrict__ inv, int N) {
    int n = blockIdx.x * blockDim.x + threadIdx.x;
    if (n < N) inv[n] = 1.0f / fmaxf(deg[n], 1.0f);
}

// z[e,j] = relu(b1[j] + [h[src]|h[dst]] . W1[:,j]);  one warp per edge, lane = j
__global__ void k_z(const float* __restrict__ h, const int* __restrict__ src,
                    const int* __restrict__ dst, const float* __restrict__ W1l,
                    const float* __restrict__ b1l, float* __restrict__ z, int E) {
    __shared__ float W1s[128 * 32];
    for (int i = threadIdx.x; i < 128 * 32; i += blockDim.x) W1s[i] = W1l[i];
    __syncthreads();
    int e = (blockIdx.x * blockDim.x + threadIdx.x) >> 5;
    int lane = threadIdx.x & 31;
    if (e >= E) return;
    int s = src[e], d = dst[e];
    const float* hs = h + s * 64;
    const float* hd = h + d * 64;
    float acc = b1l[lane];
#pragma unroll
    for (int k = 0; k < 64; k++) acc += hs[k] * W1s[k * 32 + lane];
#pragma unroll
    for (int k = 0; k < 64; k++) acc += hd[k] * W1s[(64 + k) * 32 + lane];
    z[e * 32 + lane] = fmaxf(acc, 0.f);
}

// Q = h @ W2p[l]  : [N,64] x [64,2112].  64x64 output tile per block, 256 thr.
__global__ __launch_bounds__(256) void k_qgemm(const float* __restrict__ A,
                                               const float* __restrict__ B,
                                               float* __restrict__ Q) {
    __shared__ float As[64 * 64];
    __shared__ float Bs[64 * 64];
    const int m0 = blockIdx.y * 64;
    const int n0 = blockIdx.x * 64;
    const int t = threadIdx.x;
    // A tile is a contiguous 4096-float block (full K dim)
    {
        const float4* Ag = (const float4*)(A + (size_t)m0 * 64);
        float4* As4 = (float4*)As;
#pragma unroll
        for (int i = 0; i < 4; i++) As4[t + 256 * i] = Ag[t + 256 * i];
    }
    // B tile: 64 rows of 64 floats, row stride QCOLS
    {
        int row = t >> 4;       // 0..15
        int c4 = t & 15;        // float4 index within row
#pragma unroll
        for (int i = 0; i < 4; i++) {
            int hh = row + 16 * i;
            float4 v = *(const float4*)(B + (size_t)hh * QCOLS + n0 + c4 * 4);
            *(float4*)(&Bs[hh * 64 + c4 * 4]) = v;
        }
    }
    __syncthreads();
    const int lane = t & 31;
    const int ty = t >> 5;  // 0..7
    float2 acc[8];
#pragma unroll
    for (int i = 0; i < 8; i++) acc[i] = make_float2(0.f, 0.f);
#pragma unroll
    for (int k = 0; k < 64; k++) {
        float2 b = *(const float2*)(&Bs[k * 64 + lane * 2]);
#pragma unroll
        for (int i = 0; i < 8; i++) {
            float a = As[(ty + 8 * i) * 64 + k];
            acc[i].x += a * b.x;
            acc[i].y += a * b.y;
        }
    }
#pragma unroll
    for (int i = 0; i < 8; i++) {
        int r = m0 + ty + 8 * i;
        *(float2*)(&Q[(size_t)r * QCOLS + n0 + lane * 2]) = acc[i];
    }
}

// msg[e,:] = Qb[src] + z[e,:] @ Qw[src];  scatter-add into agg[dst]
__global__ void k_msg(const float* __restrict__ Q, const float* __restrict__ z,
                      const int* __restrict__ src, const int* __restrict__ dst,
                      float* __restrict__ agg, int E) {
    int e = (blockIdx.x * blockDim.x + threadIdx.x) >> 5;
    int lane = threadIdx.x & 31;
    if (e >= E) return;
    int s = src[e], d = dst[e];
    const float2* Qs = (const float2*)(Q + (size_t)s * QCOLS);
    float zj = z[e * 32 + lane];
    float2 m = Qs[1024 + lane];  // bias part (float offset 2048)
#pragma unroll
    for (int j = 0; j < 32; j++) {
        float zz = __shfl_sync(0xffffffffu, zj, j);
        float2 q = Qs[j * 32 + lane];
        m.x += zz * q.x;
        m.y += zz * q.y;
    }
    float* ad = agg + (size_t)d * 64 + 2 * lane;
    atomicAdd(ad, m.x);
    atomicAdd(ad + 1, m.y);
}

// h_out = relu( BN( agg/deg + h@Wr + br ) ) + h
__global__ void k_node(const float* __restrict__ hin, const float* __restrict__ agg,
                       const float* __restrict__ invdeg, const float* __restrict__ Wr,
                       const float* __restrict__ br, const float* __restrict__ gamma,
                       const float* __restrict__ beta, const float* __restrict__ rmean,
                       const float* __restrict__ rvar, float* __restrict__ hout, int N) {
    int t = blockIdx.x * blockDim.x + threadIdx.x;
    if (t >= N * HID) return;
    int n = t >> 6, c = t & 63;
    const float* hr = hin + (size_t)n * 64;
    float acc = br[c];
#pragma unroll
    for (int k = 0; k < 64; k++) acc += hr[k] * Wr[k * 64 + c];
    float h2 = agg[t] * invdeg[n] + acc;
    float scale = gamma[c] * rsqrtf(rvar[c] + 1e-5f);
    h2 = (h2 - rmean[c]) * scale + beta[c];
    hout[t] = fmaxf(h2, 0.f) + hr[c];
}

// out[i] = relu([h[u]|h[v]] @ Wm1 + bm1) @ Wm2 + bm2 ; one warp per output row
__global__ void k_final(const float* __restrict__ h, const int* __restrict__ bu,
                        const int* __restrict__ bv, const float* __restrict__ Wm1,
                        const float* __restrict__ bm1, const float* __restrict__ Wm2,
                        const float* __restrict__ bm2, float* __restrict__ out,
                        int nout, int B, int npg) {
    int i = (blockIdx.x * blockDim.x + threadIdx.x) >> 5;
    int lane = threadIdx.x & 31;
    if (i >= nout) return;
    int g = i / B, b = i - g * B;
    int u = bu[b] + g * npg;
    int v = bv[b] + g * npg;
    const float* hu = h + (size_t)u * 64;
    const float* hv = h + (size_t)v * 64;
    float a0 = bm1[lane], a1 = bm1[lane + 32];
#pragma unroll
    for (int k = 0; k < 64; k++) {
        float x0 = hu[k];
        a0 += x0 * Wm1[k * 64 + lane];
        a1 += x0 * Wm1[k * 64 + lane + 32];
    }
#pragma unroll
    for (int k = 0; k < 64; k++) {
        float x1 = hv[k];
        a0 += x1 * Wm1[(64 + k) * 64 + lane];
        a1 += x1 * Wm1[(64 + k) * 64 + lane + 32];
    }
    float r = fmaxf(a0, 0.f) * Wm2[lane] + fmaxf(a1, 0.f) * Wm2[lane + 32];
#pragma unroll
    for (int off = 16; off; off >>= 1) r += __shfl_down_sync(0xffffffffu, r, off);
    if (lane == 0) out[i] = r + bm2[0];
}

extern "C" void kernel_launch(void* const* d_in, const int* in_sizes, int n_in,
                              void* d_out, int out_size) {
    const float* x   = (const float*)d_in[0];
    const int* eidx  = (const int*)d_in[1];
    const int* bu    = (const int*)d_in[2];
    const int* bv    = (const int*)d_in[3];
    // num_graphs may or may not be materialized as an input (size-1 int)
    int base = (in_sizes[4] == 1) ? 5 : 4;
    const float* Wp    = (const float*)d_in[base + 0];
    const float* bp    = (const float*)d_in[base + 1];
    const float* W1    = (const float*)d_in[base + 2];
    const float* b1    = (const float*)d_in[base + 3];
    const float* W2    = (const float*)d_in[base + 4];
    const float* b2    = (const float*)d_in[base + 5];
    const float* Wr    = (const float*)d_in[base + 6];
    const float* br    = (const float*)d_in[base + 7];
    const float* gamma = (const float*)d_in[base + 8];
    const float* beta  = (const float*)d_in[base + 9];
    const float* rmean = (const float*)d_in[base + 10];
    const float* rvar  = (const float*)d_in[base + 11];
    const float* Wm1   = (const float*)d_in[base + 12];
    const float* bm1   = (const float*)d_in[base + 13];
    const float* Wm2   = (const float*)d_in[base + 14];
    const float* bm2   = (const float*)d_in[base + 15];

    const int Nn = in_sizes[0] / 8;     // 15360
    const int E  = in_sizes[1] / 2;     // 41984
    const int B  = in_sizes[2];         // 41
    const int G  = out_size / B;        // 512
    const int npg = Nn / G;             // 30
    const int* src = eidx;
    const int* dst = eidx + E;

    static float *p_h0 = nullptr, *p_h1, *p_Q, *p_z, *p_agg, *p_deg, *p_invdeg;
    if (!p_h0) {
        cudaGetSymbolAddress((void**)&p_h0, g_h0);
        cudaGetSymbolAddress((void**)&p_h1, g_h1);
        cudaGetSymbolAddress((void**)&p_Q, g_Q);
        cudaGetSymbolAddress((void**)&p_z, g_z);
        cudaGetSymbolAddress((void**)&p_agg, g_agg);
        cudaGetSymbolAddress((void**)&p_deg, g_deg);
        cudaGetSymbolAddress((void**)&p_invdeg, g_invdeg);
    }
    float* p_W2p;
    cudaGetSymbolAddress((void**)&p_W2p, g_W2p);

    // one-time prep (re-done every call: deterministic, cheap)
    k_w2p<<<(NLAYERS * HID * QCOLS + 255) / 256, 256>>>(W2, b2);
    k_zero<<<(Nn + 255) / 256, 256>>>(p_deg, Nn);
    k_proj<<<(Nn * HID + 255) / 256, 256>>>(x, Wp, bp, p_h0, Nn);
    k_deg<<<(E + 255) / 256, 256>>>(dst, p_deg, E);
    k_invdeg<<<(Nn + 255) / 256, 256>>>(p_deg, p_invdeg, Nn);

    float* cur = p_h0;
    float* nxt = p_h1;
    for (int l = 0; l < NLAYERS; l++) {
        k_zero<<<(Nn * HID + 255) / 256, 256>>>(p_agg, Nn * HID);
        k_z<<<(E + 3) / 4, 128>>>(cur, src, dst, W1 + (size_t)l * 128 * 32,
                                  b1 + (size_t)l * 32, p_z, E);
        dim3 gq(QCOLS / 64, Nn / 64);
        k_qgemm<<<gq, 256>>>(cur, p_W2p + (size_t)l * HID * QCOLS, p_Q);
        k_msg<<<(E + 7) / 8, 256>>>(p_Q, p_z, src, dst, p_agg, E);
        k_node<<<(Nn * HID + 255) / 256, 256>>>(
            cur, p_agg, p_invdeg, Wr + (size_t)l * 64 * 64, br + (size_t)l * 64,
            gamma + (size_t)l * 64, beta + (size_t)l * 64, rmean + (size_t)l * 64,
            rvar + (size_t)l * 64, nxt, Nn);
        float* tmp = cur; cur = nxt; nxt = tmp;
    }
    k_final<<<(out_size + 7) / 8, 256>>>(cur, bu, bv, Wm1, bm1, Wm2, bm2,
                                         (float*)d_out, out_size, B, npg);
}